// round 5
// baseline (speedup 1.0000x reference)
#include <cuda_runtime.h>
#include <cuda_bf16.h>
#include <cstdint>

// ============================================================
// MADE/IAF flow step via int8 tensor-core IMMA (m16n8k32.s8.s32).
// fp32-class accuracy via 16-bit fixed-point split per operand:
//   x ~= dlt * q,  q = hi*256 + lo  (hi,lo int8, |q| <= 32639)
//   qa*qb = 65536*hi*hi + 256*(hi*lo + lo*hi) [+ lo*lo dropped]
// GEMM1: h = relu(zp @ (W1*M1) + b1)   [4096,1024]x[1024,4096]
// GEMM2: res = h @ (W2*M2) + b2        [4096,4096]x[4096,2048]
// finish: x = zp*exp(log_s)+mu (inv-permuted), log_det = row-sum
// ============================================================

// ---------------- device scratch (no allocs allowed) ----------------
__device__ float g_res[4096ull * 2048ull];   // gemm2 out (fp32)
__device__ float g_hf[4096ull * 4096ull];    // gemm1 out (fp32)
__device__ int   g_inv[4096];
__device__ char  g_zhi[4096ull * 1024ull],  g_zlo[4096ull * 1024ull];   // [B,D]
__device__ char  g_w1hi[4096ull * 1024ull], g_w1lo[4096ull * 1024ull];  // [N=4096,K=1024]
__device__ char  g_hqhi[4096ull * 4096ull], g_hqlo[4096ull * 4096ull];  // [B,H]
__device__ char  g_w2hi[2048ull * 4096ull], g_w2lo[2048ull * 4096ull];  // [N=2048,K=4096]
__device__ float g_amz[4096], g_am1[4096], g_am2[2048], g_amh[4096];    // per-row/col amax

// ---------------- PTX helpers (all baseline sm_80+ PTX) ----------------
__device__ __forceinline__ uint32_t smem_u32(const void* p) {
    uint32_t a;
    asm("{ .reg .u64 t; cvta.to.shared.u64 t, %1; cvt.u32.u64 %0, t; }" : "=r"(a) : "l"(p));
    return a;
}
__device__ __forceinline__ void cp16(uint32_t s, const void* g) {
    asm volatile("cp.async.cg.shared.global [%0], [%1], 16;" :: "r"(s), "l"(g));
}
__device__ __forceinline__ void cp_commit() {
    asm volatile("cp.async.commit_group;" ::: "memory");
}
__device__ __forceinline__ void cp_wait1() {
    asm volatile("cp.async.wait_group 1;" ::: "memory");
}
__device__ __forceinline__ void ldm_x4(uint32_t addr, uint32_t* r) {
    asm volatile("ldmatrix.sync.aligned.m8n8.x4.shared.b16 {%0,%1,%2,%3}, [%4];"
                 : "=r"(r[0]), "=r"(r[1]), "=r"(r[2]), "=r"(r[3]) : "r"(addr));
}
__device__ __forceinline__ void mma_s8(int* c, const uint32_t* a, const uint32_t* b) {
    asm volatile(
        "mma.sync.aligned.m16n8k32.row.col.s32.s8.s8.s32 "
        "{%0,%1,%2,%3}, {%4,%5,%6,%7}, {%8,%9}, {%0,%1,%2,%3};"
        : "+r"(c[0]), "+r"(c[1]), "+r"(c[2]), "+r"(c[3])
        : "r"(a[0]), "r"(a[1]), "r"(a[2]), "r"(a[3]), "r"(b[0]), "r"(b[1]));
}

// 16-bit fixed-point quantize: q = hi*256 + lo, lo in [-128,127]
__device__ __forceinline__ void quant16(float v, float inv, char& h8, char& l8) {
    int q = __float2int_rn(v * inv);
    q = max(-32639, min(32639, q));
    int h = (q + 128) >> 8;
    int l = q - (h << 8);
    h8 = (char)h;
    l8 = (char)l;
}

// ---------------- prep kernels ----------------
__global__ void build_inv(const int* __restrict__ perm, int D) {
    int d = blockIdx.x * blockDim.x + threadIdx.x;
    if (d < D) g_inv[perm[d]] = d;
}

__global__ void init_amax() {
    int t = blockIdx.x * blockDim.x + threadIdx.x;
    if (t < 4096) { g_amz[t] = 0.f; g_amh[t] = 0.f; g_am1[t] = 0.f; }
    if (t < 2048) g_am2[t] = 0.f;
}

// quantize z rows (gathered by perm; amax is perm-invariant)
__global__ void quant_z(const float* __restrict__ z, const int* __restrict__ perm, int D) {
    const int i = blockIdx.x;
    const int t = threadIdx.x;
    __shared__ float red[256];
    float m = 0.f;
    for (int k = t; k < D; k += 256) m = fmaxf(m, fabsf(z[(size_t)i * D + k]));
    red[t] = m;
    __syncthreads();
    for (int off = 128; off > 0; off >>= 1) {
        if (t < off) red[t] = fmaxf(red[t], red[t + off]);
        __syncthreads();
    }
    const float a = red[0];
    if (t == 0) g_amz[i] = a;
    const float inv = a > 0.f ? 32639.f / a : 0.f;
    for (int k = t; k < D; k += 256) {
        float v = z[(size_t)i * D + perm[k]];
        char h8, l8;
        quant16(v, inv, h8, l8);
        g_zhi[(size_t)i * D + k] = h8;
        g_zlo[(size_t)i * D + k] = l8;
    }
}

// masked per-output-column amax of W [K,N] -> am[n]
// mode 1: mask = (n % 1023) >= k ; mode 2: mask = (n % 1024) > (k % 1023)
__global__ void w_amax(const float* __restrict__ W, float* __restrict__ am,
                       int K, int N, int mode) {
    __shared__ float s[8][32];
    const int n = blockIdx.x * 32 + threadIdx.x;
    const int k0 = blockIdx.y * 256;
    float m = 0.f;
#pragma unroll 4
    for (int j = 0; j < 32; j++) {
        int k = k0 + threadIdx.y + j * 8;
        float v = W[(size_t)k * N + n];
        bool msk = (mode == 1) ? ((n % 1023) >= k) : ((n & 1023) > (k % 1023));
        m = fmaxf(m, msk ? fabsf(v) : 0.f);
    }
    s[threadIdx.y][threadIdx.x] = m;
    __syncthreads();
    if (threadIdx.y == 0) {
#pragma unroll
        for (int j = 1; j < 8; j++) m = fmaxf(m, s[j][threadIdx.x]);
        atomicMax((int*)&am[n], __float_as_int(m));
    }
}

// mask + transpose + quantize: W [K,N] fp32 -> [N,K] int8 hi/lo
__global__ void w_quant(const float* __restrict__ W, const float* __restrict__ am,
                        char* __restrict__ oHi, char* __restrict__ oLo,
                        int K, int N, int mode) {
    __shared__ float tile[32][33];
    const int k0 = blockIdx.y * 32;
    const int n0 = blockIdx.x * 32;
    const int tx = threadIdx.x;   // 32
    const int ty = threadIdx.y;   // 8
#pragma unroll
    for (int j = 0; j < 32; j += 8)
        tile[ty + j][tx] = W[(size_t)(k0 + ty + j) * N + n0 + tx];
    __syncthreads();
#pragma unroll
    for (int j = 0; j < 32; j += 8) {
        int n = n0 + ty + j;
        int k = k0 + tx;
        float v = tile[tx][ty + j];
        bool msk = (mode == 1) ? ((n % 1023) >= k) : ((n & 1023) > (k % 1023));
        v = msk ? v : 0.f;
        float a = am[n];
        float inv = a > 0.f ? 32639.f / a : 0.f;
        char h8, l8;
        quant16(v, inv, h8, l8);
        oHi[(size_t)n * K + k] = h8;
        oLo[(size_t)n * K + k] = l8;
    }
}

// quantize h rows using g_amh (filled by gemm1 epilogue atomics)
__global__ void quant_h(int H) {
    const int i = blockIdx.x;
    const int t = threadIdx.x;
    const float a = g_amh[i];
    const float inv = a > 0.f ? 32639.f / a : 0.f;
    for (int j = t; j < H; j += 256) {
        float v = g_hf[(size_t)i * H + j];
        char h8, l8;
        quant16(v, inv, h8, l8);
        g_hqhi[(size_t)i * H + j] = h8;
        g_hqlo[(size_t)i * H + j] = l8;
    }
}

// ---------------- int8 IMMA GEMM (split 16-bit fixed point) ----------------
// C[m,n] = dA[m]*dB[n]*(65536*HH + 256*XX) + bias[n]
// A [M,K] row-major hi/lo int8, B [N,K] row-major hi/lo int8.
// CTA 128x128, K-chunk 64, 8 warps (2x4), warp tile 64x32, 3-stage cp.async.
// Smem row: 128B = [0,64) hi k-bytes, [64,128) lo k-bytes, XOR-swizzled.
#define SA_BYTES   16384
#define STG_BYTES  32768
#define SM_TOTAL   (3 * STG_BYTES)

template <int MODE>
__global__ __launch_bounds__(256, 1) void gemm_imma(
    const char* __restrict__ Ahi, const char* __restrict__ Alo,
    const char* __restrict__ Bhi, const char* __restrict__ Blo,
    const float* __restrict__ amA, const float* __restrict__ amB,
    const float* __restrict__ bias, int K, int Nout,
    float* __restrict__ outF, float* __restrict__ rowAmax)
{
    extern __shared__ char smem[];
    const uint32_t sb = smem_u32(smem);
    const int tid  = threadIdx.x;
    const int lane = tid & 31;
    const int w    = tid >> 5;
    const int wm   = w & 1;        // 2 warps in M
    const int wn   = w >> 1;       // 4 warps in N
    const int row0 = blockIdx.y * 128;
    const int col0 = blockIdx.x * 128;
    const int nk   = K >> 6;

    int hh[4][4][4], xx[4][4][4];
#pragma unroll
    for (int mt = 0; mt < 4; mt++)
#pragma unroll
        for (int nt = 0; nt < 4; nt++)
#pragma unroll
            for (int e = 0; e < 4; e++) { hh[mt][nt][e] = 0; xx[mt][nt][e] = 0; }

    auto load_stage = [&](int t) {
        const int k0 = t << 6;
        const uint32_t s0 = sb + (t % 3) * STG_BYTES;
#pragma unroll
        for (int i = 0; i < 4; i++) {
            int idx = tid + i * 256;
            int row = idx >> 3, cc = idx & 7;
            const char* src = ((cc < 4) ? Ahi : Alo)
                            + (size_t)(row0 + row) * K + k0 + (cc & 3) * 16;
            cp16(s0 + row * 128 + ((cc * 16) ^ ((row & 7) << 4)), src);
        }
#pragma unroll
        for (int i = 0; i < 4; i++) {
            int idx = tid + i * 256;
            int row = idx >> 3, cc = idx & 7;
            const char* src = ((cc < 4) ? Bhi : Blo)
                            + (size_t)(col0 + row) * K + k0 + (cc & 3) * 16;
            cp16(s0 + SA_BYTES + row * 128 + ((cc * 16) ^ ((row & 7) << 4)), src);
        }
    };

    load_stage(0); cp_commit();
    load_stage(1); cp_commit();

    // fragment address components (byte-identical to the validated bf16 layout)
    int rA[4], xA[4];
#pragma unroll
    for (int mt = 0; mt < 4; mt++) {
        int r = wm * 64 + mt * 16 + (lane & 15);
        rA[mt] = r * 128;
        xA[mt] = (r & 7) << 4;
    }
    const int kA2 = (lane >> 4) << 4;
    int rB[2], xB[2];
#pragma unroll
    for (int p = 0; p < 2; p++) {
        int r = wn * 32 + p * 16 + (lane & 7) + ((lane & 16) >> 1);
        rB[p] = r * 128;
        xB[p] = (r & 7) << 4;
    }
    const int kB2 = (lane & 8) << 1;

    for (int t = 0; t < nk; t++) {
        cp_wait1();
        __syncthreads();
        if (t + 2 < nk) load_stage(t + 2);
        cp_commit();

        const uint32_t sA = sb + (t % 3) * STG_BYTES;
        const uint32_t sB = sA + SA_BYTES;
#pragma unroll
        for (int ks = 0; ks < 2; ks++) {
            uint32_t Ah[4][4], Al[4][4], Bh[4][2], Bl[4][2];
            const int kbA = ks * 32 + kA2;
            const int kbB = ks * 32 + kB2;
#pragma unroll
            for (int mt = 0; mt < 4; mt++)
                ldm_x4(sA + rA[mt] + (kbA ^ xA[mt]), Ah[mt]);
#pragma unroll
            for (int mt = 0; mt < 4; mt++)
                ldm_x4(sA + rA[mt] + ((64 + kbA) ^ xA[mt]), Al[mt]);
#pragma unroll
            for (int p = 0; p < 2; p++) {
                uint32_t r4[4];
                ldm_x4(sB + rB[p] + (kbB ^ xB[p]), r4);
                Bh[2 * p][0] = r4[0]; Bh[2 * p][1] = r4[1];
                Bh[2 * p + 1][0] = r4[2]; Bh[2 * p + 1][1] = r4[3];
            }
#pragma unroll
            for (int p = 0; p < 2; p++) {
                uint32_t r4[4];
                ldm_x4(sB + rB[p] + ((64 + kbB) ^ xB[p]), r4);
                Bl[2 * p][0] = r4[0]; Bl[2 * p][1] = r4[1];
                Bl[2 * p + 1][0] = r4[2]; Bl[2 * p + 1][1] = r4[3];
            }
#pragma unroll
            for (int mt = 0; mt < 4; mt++)
#pragma unroll
                for (int nt = 0; nt < 4; nt++) {
                    mma_s8(hh[mt][nt], Ah[mt], Bh[nt]);   // hi*hi
                    mma_s8(xx[mt][nt], Ah[mt], Bl[nt]);   // hi*lo
                    mma_s8(xx[mt][nt], Al[mt], Bh[nt]);   // lo*hi
                }
        }
    }

    // epilogue
    const float Q = 1.f / (32639.f * 32639.f);
    const int mrow = lane >> 2;
    const int mcol = (lane & 3) * 2;
#pragma unroll
    for (int mt = 0; mt < 4; mt++) {
#pragma unroll
        for (int hf = 0; hf < 2; hf++) {
            const int r = row0 + wm * 64 + mt * 16 + mrow + hf * 8;
            const float sa = amA[r] * Q;
            float vmax = 0.f;
#pragma unroll
            for (int nt = 0; nt < 4; nt++) {
                const int c = col0 + wn * 32 + nt * 8 + mcol;
                float v0 = sa * amB[c]
                         * fmaf(65536.f, (float)hh[mt][nt][2 * hf],
                                256.f * (float)xx[mt][nt][2 * hf]) + bias[c];
                float v1 = sa * amB[c + 1]
                         * fmaf(65536.f, (float)hh[mt][nt][2 * hf + 1],
                                256.f * (float)xx[mt][nt][2 * hf + 1]) + bias[c + 1];
                if (MODE == 1) {
                    v0 = fmaxf(v0, 0.f);
                    v1 = fmaxf(v1, 0.f);
                    vmax = fmaxf(vmax, fmaxf(v0, v1));
                }
                *(float2*)(outF + (size_t)r * Nout + c) = make_float2(v0, v1);
            }
            if (MODE == 1) atomicMax((int*)&rowAmax[r], __float_as_int(vmax));
        }
    }
}

// ---------------- finish ----------------
__global__ void finish_kernel(const float* __restrict__ z,
                              const int* __restrict__ perm,
                              float* __restrict__ out,
                              int Bn, int D)
{
    const int i = blockIdx.x;
    const int t = threadIdx.x;
    __shared__ float red[256];

    const float* resrow = &g_res[(size_t)i * 2 * D];
    const float* zrow   = &z[(size_t)i * D];

    float s = 0.f;
    for (int d = t; d < D; d += blockDim.x) s += resrow[D + d];

    for (int j = t; j < D; j += blockDim.x) {
        int dj   = g_inv[j];
        float ls = resrow[D + dj];
        float mu = resrow[dj];
        float zp = zrow[perm[dj]];
        out[(size_t)i * D + j] = fmaf(zp, expf(ls), mu);
    }

    red[t] = s;
    __syncthreads();
    for (int off = 128; off > 0; off >>= 1) {
        if (t < off) red[t] += red[t + off];
        __syncthreads();
    }
    if (t == 0) out[(size_t)Bn * D + i] = red[0];
}

// ---------------- launch ----------------
extern "C" void kernel_launch(void* const* d_in, const int* in_sizes, int n_in,
                              void* d_out, int out_size) {
    const float* z    = (const float*)d_in[0];
    const float* W1   = (const float*)d_in[1];
    const float* b1   = (const float*)d_in[2];
    const float* W2   = (const float*)d_in[3];
    const float* b2   = (const float*)d_in[4];
    const int*   perm = (const int*)d_in[5];

    const int D  = in_sizes[5];      // 1024
    const int H  = in_sizes[2];      // 4096
    const int N2 = in_sizes[4];      // 2048
    const int B  = in_sizes[0] / D;  // 4096

    cudaFuncSetAttribute(gemm_imma<1>, cudaFuncAttributeMaxDynamicSharedMemorySize, SM_TOTAL);
    cudaFuncSetAttribute(gemm_imma<2>, cudaFuncAttributeMaxDynamicSharedMemorySize, SM_TOTAL);

    char *zhi, *zlo, *w1hi, *w1lo, *hqhi, *hqlo, *w2hi, *w2lo;
    float *res, *hf, *amz, *am1, *am2, *amh;
    cudaGetSymbolAddress((void**)&zhi,  g_zhi);
    cudaGetSymbolAddress((void**)&zlo,  g_zlo);
    cudaGetSymbolAddress((void**)&w1hi, g_w1hi);
    cudaGetSymbolAddress((void**)&w1lo, g_w1lo);
    cudaGetSymbolAddress((void**)&hqhi, g_hqhi);
    cudaGetSymbolAddress((void**)&hqlo, g_hqlo);
    cudaGetSymbolAddress((void**)&w2hi, g_w2hi);
    cudaGetSymbolAddress((void**)&w2lo, g_w2lo);
    cudaGetSymbolAddress((void**)&res,  g_res);
    cudaGetSymbolAddress((void**)&hf,   g_hf);
    cudaGetSymbolAddress((void**)&amz,  g_amz);
    cudaGetSymbolAddress((void**)&am1,  g_am1);
    cudaGetSymbolAddress((void**)&am2,  g_am2);
    cudaGetSymbolAddress((void**)&amh,  g_amh);

    build_inv<<<(D + 255) / 256, 256>>>(perm, D);
    init_amax<<<16, 256>>>();
    quant_z<<<B, 256>>>(z, perm, D);
    w_amax<<<dim3(H / 32,  D / 256), dim3(32, 8)>>>(W1, am1, D, H, 1);
    w_amax<<<dim3(N2 / 32, H / 256), dim3(32, 8)>>>(W2, am2, H, N2, 2);
    w_quant<<<dim3(H / 32,  D / 32), dim3(32, 8)>>>(W1, am1, w1hi, w1lo, D, H, 1);
    w_quant<<<dim3(N2 / 32, H / 32), dim3(32, 8)>>>(W2, am2, w2hi, w2lo, H, N2, 2);

    // GEMM1: [B,D] x packed-W1 -> h fp32 (+ row amax)
    gemm_imma<1><<<dim3(H / 128, B / 128), 256, SM_TOTAL>>>(
        zhi, zlo, w1hi, w1lo, amz, am1, b1, D, H, hf, amh);
    quant_h<<<B, 256>>>(H);
    // GEMM2: [B,H] x packed-W2 -> res fp32
    gemm_imma<2><<<dim3(N2 / 128, B / 128), 256, SM_TOTAL>>>(
        hqhi, hqlo, w2hi, w2lo, amh, am2, b2, H, N2, res, nullptr);

    finish_kernel<<<B, 256>>>(z, perm, (float*)d_out, B, D);
}

// round 6
// speedup vs baseline: 3.7353x; 3.7353x over previous
#include <cuda_runtime.h>
#include <cuda_bf16.h>
#include <cstdint>

// ============================================================
// MADE/IAF flow step on tensor cores via mma.sync (bf16, HMMA),
// fp32 accuracy via 3-term bf16 split: x*y ~= hi*hi + lo*hi + hi*lo
// + MADE-mask block sparsity: k-chunks that the mask zeroes for a
//   whole 128-wide output-column tile are skipped exactly (~44%).
// GEMM1: h = relu(zp @ (W1*M1) + b1)   [4096,1024]x[1024,4096]
// GEMM2: res = h @ (W2*M2) + b2        [4096,4096]x[4096,2048]
// finish: x = zp*exp(log_s)+mu (inv-permuted), log_det = row-sum
// ============================================================

// ---------------- device scratch (no allocs allowed) ----------------
__device__ float         g_res[4096ull * 2048ull];   // gemm2 out (fp32)
__device__ int           g_inv[4096];
__device__ __nv_bfloat16 g_zhi[4096ull * 1024ull], g_zlo[4096ull * 1024ull];   // [B,D]
__device__ __nv_bfloat16 g_w1hi[4096ull * 1024ull], g_w1lo[4096ull * 1024ull]; // [N=4096,K=1024]
__device__ __nv_bfloat16 g_hhi[4096ull * 4096ull], g_hlo[4096ull * 4096ull];   // [B,H]
__device__ __nv_bfloat16 g_w2hi[2048ull * 4096ull], g_w2lo[2048ull * 4096ull]; // [N=2048,K=4096]

// ---------------- PTX helpers (all baseline sm_80+ PTX) ----------------
__device__ __forceinline__ uint32_t smem_u32(const void* p) {
    uint32_t a;
    asm("{ .reg .u64 t; cvta.to.shared.u64 t, %1; cvt.u32.u64 %0, t; }" : "=r"(a) : "l"(p));
    return a;
}
__device__ __forceinline__ void cp16(uint32_t s, const void* g) {
    asm volatile("cp.async.cg.shared.global [%0], [%1], 16;" :: "r"(s), "l"(g));
}
__device__ __forceinline__ void cp_commit() {
    asm volatile("cp.async.commit_group;" ::: "memory");
}
__device__ __forceinline__ void cp_wait1() {
    asm volatile("cp.async.wait_group 1;" ::: "memory");
}
__device__ __forceinline__ void ldm_x4(uint32_t addr, uint32_t* r) {
    asm volatile("ldmatrix.sync.aligned.m8n8.x4.shared.b16 {%0,%1,%2,%3}, [%4];"
                 : "=r"(r[0]), "=r"(r[1]), "=r"(r[2]), "=r"(r[3]) : "r"(addr));
}
__device__ __forceinline__ void mma16816(float* c, const uint32_t* a, const uint32_t* b) {
    asm volatile(
        "mma.sync.aligned.m16n8k16.row.col.f32.bf16.bf16.f32 "
        "{%0,%1,%2,%3}, {%4,%5,%6,%7}, {%8,%9}, {%0,%1,%2,%3};"
        : "+f"(c[0]), "+f"(c[1]), "+f"(c[2]), "+f"(c[3])
        : "r"(a[0]), "r"(a[1]), "r"(a[2]), "r"(a[3]), "r"(b[0]), "r"(b[1]));
}

// ---------------- prep kernels ----------------
__global__ void build_inv(const int* __restrict__ perm, int D) {
    int d = blockIdx.x * blockDim.x + threadIdx.x;
    if (d < D) g_inv[perm[d]] = d;
}

__global__ void split_z_kernel(const float* __restrict__ z, const int* __restrict__ perm,
                               int D, long total) {
    long idx = (long)blockIdx.x * blockDim.x + threadIdx.x;
    if (idx >= total) return;
    int i = (int)(idx >> 10);      // D = 1024
    int k = (int)(idx & 1023);
    float v = z[(size_t)i * D + perm[k]];
    __nv_bfloat16 hi = __float2bfloat16(v);
    __nv_bfloat16 lo = __float2bfloat16(v - __bfloat162float(hi));
    g_zhi[idx] = hi;
    g_zlo[idx] = lo;
}

// mask+transpose+split: in W [K,N] fp32 -> out [N,K] bf16 hi/lo
// mode 1: mask = (n % 1023) >= k          (W1/M1)
// mode 2: mask = (n % 1024) > (k % 1023)  (W2/M2)
__global__ void prep_w_kernel(const float* __restrict__ W,
                              __nv_bfloat16* __restrict__ oHi, __nv_bfloat16* __restrict__ oLo,
                              int K, int N, int mode) {
    __shared__ float tile[32][33];
    const int k0 = blockIdx.y * 32;
    const int n0 = blockIdx.x * 32;
    const int tx = threadIdx.x;   // 32
    const int ty = threadIdx.y;   // 8
#pragma unroll
    for (int j = 0; j < 32; j += 8)
        tile[ty + j][tx] = W[(size_t)(k0 + ty + j) * N + n0 + tx];
    __syncthreads();
#pragma unroll
    for (int j = 0; j < 32; j += 8) {
        int n = n0 + ty + j;
        int k = k0 + tx;
        float v = tile[tx][ty + j];
        bool m;
        if (mode == 1) m = (n % 1023) >= k;
        else           m = (n % 1024) > (k % 1023);
        v = m ? v : 0.0f;
        __nv_bfloat16 hi = __float2bfloat16(v);
        __nv_bfloat16 lo = __float2bfloat16(v - __bfloat162float(hi));
        oHi[(size_t)n * K + k] = hi;
        oLo[(size_t)n * K + k] = lo;
    }
}

// ---------------- mma.sync GEMM (3-term bf16 split, chunk skipping) ----------------
// C[m,n] = sum_k A[m,k]*B[n,k]; A [M,K] row-major hi/lo, B [N,K] row-major hi/lo.
// CTA tile 128x128, K-chunk 32, 8 warps (2x4), warp tile 64x32, 3-stage cp.async.
// Smem row layout: 128 rows x 128B; bytes [0,64) = hi k0..31, [64,128) = lo k0..31,
// XOR-swizzled: byte = row*128 + (inner ^ ((row&7)<<4)).
// Per-CTA kept-chunk list skips k-chunks the MADE mask fully zeroes for this n-tile.
#define SA_BYTES   16384
#define STG_BYTES  32768
#define SM_TOTAL   (3 * STG_BYTES + 1024)

template <int MODE>
__global__ __launch_bounds__(256, 1) void gemm_mma(
    const __nv_bfloat16* __restrict__ Ahi, const __nv_bfloat16* __restrict__ Alo,
    const __nv_bfloat16* __restrict__ Bhi, const __nv_bfloat16* __restrict__ Blo,
    const float* __restrict__ bias, int K, int Nout,
    float* __restrict__ outF,
    __nv_bfloat16* __restrict__ outHi, __nv_bfloat16* __restrict__ outLo)
{
    extern __shared__ char smem[];
    const uint32_t sb = smem_u32(smem);
    int* kt = (int*)(smem + 3 * STG_BYTES);
    const int tid  = threadIdx.x;
    const int lane = tid & 31;
    const int w    = tid >> 5;
    const int wm   = w & 1;        // 2 warps in M
    const int wn   = w >> 1;       // 4 warps in N
    const int row0 = blockIdx.y * 128;
    const int col0 = blockIdx.x * 128;
    const int nk   = K >> 5;

    // ---- build kept-chunk list (mask-induced block sparsity) ----
    if (tid == 0) {
        int c = 0;
        for (int t = 0; t < nk; t++) {
            const int k0 = t << 5;
            bool keep;
            if (MODE == 1) {
                // M1 nonzero iff (j%1023) >= k; tile j%1023 in [c0, c0+127] (clamp wrap)
                int c0 = col0 % 1023;
                int jmmax = (c0 + 127 > 1022) ? 1022 : (c0 + 127);
                keep = (k0 <= jmmax);
            } else {
                // M2 nonzero iff (j%1024) > (k%1023); chunk fully zero iff
                // km0 >= jdmax and the chunk doesn't wrap mod 1023.
                int km0 = k0 % 1023;
                int jdmax = (col0 & 1023) + 127;
                keep = (km0 < jdmax) || (km0 > 991);
            }
            if (keep) kt[c++] = t;
        }
        kt[255] = c;
    }
    __syncthreads();
    const int cnt = kt[255];

    float acc[4][4][4];
#pragma unroll
    for (int mt = 0; mt < 4; mt++)
#pragma unroll
        for (int nt = 0; nt < 4; nt++)
#pragma unroll
            for (int e = 0; e < 4; e++) acc[mt][nt][e] = 0.f;

    auto load_stage = [&](int chunk, int slot) {
        const int k0 = chunk << 5;
        const uint32_t s0 = sb + slot * STG_BYTES;
#pragma unroll
        for (int i = 0; i < 4; i++) {
            int idx = tid + i * 256;
            int row = idx >> 3, cc = idx & 7;
            const __nv_bfloat16* src =
                ((cc < 4) ? Ahi : Alo) + (size_t)(row0 + row) * K + k0 + (cc & 3) * 8;
            cp16(s0 + row * 128 + ((cc * 16) ^ ((row & 7) << 4)), src);
        }
#pragma unroll
        for (int i = 0; i < 4; i++) {
            int idx = tid + i * 256;
            int row = idx >> 3, cc = idx & 7;
            const __nv_bfloat16* src =
                ((cc < 4) ? Bhi : Blo) + (size_t)(col0 + row) * K + k0 + (cc & 3) * 8;
            cp16(s0 + SA_BYTES + row * 128 + ((cc * 16) ^ ((row & 7) << 4)), src);
        }
    };

    load_stage(kt[0], 0);
    cp_commit();
    if (cnt > 1) load_stage(kt[1], 1);
    cp_commit();

    // fragment address components (per-thread constants)
    int rA[4], xA[4];
#pragma unroll
    for (int mt = 0; mt < 4; mt++) {
        int r = wm * 64 + mt * 16 + (lane & 15);
        rA[mt] = r * 128;
        xA[mt] = (r & 7) << 4;
    }
    const int kA2 = (lane >> 4) << 4;          // A k-byte offset part (0 or 16)
    int rB[2], xB[2];
#pragma unroll
    for (int p = 0; p < 2; p++) {
        int r = wn * 32 + p * 16 + (lane & 7) + ((lane & 16) >> 1);
        rB[p] = r * 128;
        xB[p] = (r & 7) << 4;
    }
    const int kB2 = (lane & 8) << 1;           // B k-byte offset part (0 or 16)

    for (int i = 0; i < cnt; i++) {
        cp_wait1();
        __syncthreads();
        if (i + 2 < cnt) load_stage(kt[i + 2], (i + 2) % 3);
        cp_commit();

        const uint32_t sA = sb + (i % 3) * STG_BYTES;
        const uint32_t sB = sA + SA_BYTES;
#pragma unroll
        for (int ks = 0; ks < 2; ks++) {
            uint32_t Ah[4][4], Al[4][4], Bh[4][2], Bl[4][2];
            const int kbA = ks * 32 + kA2;
            const int kbB = ks * 32 + kB2;
#pragma unroll
            for (int mt = 0; mt < 4; mt++)
                ldm_x4(sA + rA[mt] + (kbA ^ xA[mt]), Ah[mt]);
#pragma unroll
            for (int mt = 0; mt < 4; mt++)
                ldm_x4(sA + rA[mt] + ((64 + kbA) ^ xA[mt]), Al[mt]);
#pragma unroll
            for (int p = 0; p < 2; p++) {
                uint32_t r4[4];
                ldm_x4(sB + rB[p] + (kbB ^ xB[p]), r4);
                Bh[2 * p][0] = r4[0]; Bh[2 * p][1] = r4[1];
                Bh[2 * p + 1][0] = r4[2]; Bh[2 * p + 1][1] = r4[3];
            }
#pragma unroll
            for (int p = 0; p < 2; p++) {
                uint32_t r4[4];
                ldm_x4(sB + rB[p] + ((64 + kbB) ^ xB[p]), r4);
                Bl[2 * p][0] = r4[0]; Bl[2 * p][1] = r4[1];
                Bl[2 * p + 1][0] = r4[2]; Bl[2 * p + 1][1] = r4[3];
            }
            // hi*hi
#pragma unroll
            for (int mt = 0; mt < 4; mt++)
#pragma unroll
                for (int nt = 0; nt < 4; nt++)
                    mma16816(acc[mt][nt], Ah[mt], Bh[nt]);
            // lo*hi
#pragma unroll
            for (int mt = 0; mt < 4; mt++)
#pragma unroll
                for (int nt = 0; nt < 4; nt++)
                    mma16816(acc[mt][nt], Al[mt], Bh[nt]);
            // hi*lo
#pragma unroll
            for (int mt = 0; mt < 4; mt++)
#pragma unroll
                for (int nt = 0; nt < 4; nt++)
                    mma16816(acc[mt][nt], Ah[mt], Bl[nt]);
        }
    }

    // epilogue
    const int mrow = lane >> 2;
    const int mcol = (lane & 3) * 2;
#pragma unroll
    for (int mt = 0; mt < 4; mt++) {
        const int rbase = row0 + wm * 64 + mt * 16 + mrow;
#pragma unroll
        for (int nt = 0; nt < 4; nt++) {
            const int c = col0 + wn * 32 + nt * 8 + mcol;
            const float b0 = bias[c], b1 = bias[c + 1];
#pragma unroll
            for (int h = 0; h < 2; h++) {
                const int r = rbase + h * 8;
                float v0 = acc[mt][nt][2 * h + 0] + b0;
                float v1 = acc[mt][nt][2 * h + 1] + b1;
                const size_t o = (size_t)r * Nout + c;
                if (MODE == 1) {
                    v0 = fmaxf(v0, 0.f);
                    v1 = fmaxf(v1, 0.f);
                    __nv_bfloat16 h0 = __float2bfloat16(v0);
                    __nv_bfloat16 h1 = __float2bfloat16(v1);
                    __nv_bfloat16 l0 = __float2bfloat16(v0 - __bfloat162float(h0));
                    __nv_bfloat16 l1 = __float2bfloat16(v1 - __bfloat162float(h1));
                    __nv_bfloat162 ph; ph.x = h0; ph.y = h1;
                    __nv_bfloat162 pl; pl.x = l0; pl.y = l1;
                    *(__nv_bfloat162*)(outHi + o) = ph;
                    *(__nv_bfloat162*)(outLo + o) = pl;
                } else {
                    *(float2*)(outF + o) = make_float2(v0, v1);
                }
            }
        }
    }
}

// ---------------- finish ----------------
__global__ void finish_kernel(const float* __restrict__ z,
                              const int* __restrict__ perm,
                              float* __restrict__ out,
                              int Bn, int D)
{
    const int i = blockIdx.x;
    const int t = threadIdx.x;
    __shared__ float red[256];

    const float* resrow = &g_res[(size_t)i * 2 * D];
    const float* zrow   = &z[(size_t)i * D];

    float s = 0.f;
    for (int d = t; d < D; d += blockDim.x) s += resrow[D + d];

    for (int j = t; j < D; j += blockDim.x) {
        int dj   = g_inv[j];
        float ls = resrow[D + dj];
        float mu = resrow[dj];
        float zp = zrow[perm[dj]];
        out[(size_t)i * D + j] = fmaf(zp, expf(ls), mu);
    }

    red[t] = s;
    __syncthreads();
    for (int off = 128; off > 0; off >>= 1) {
        if (t < off) red[t] += red[t + off];
        __syncthreads();
    }
    if (t == 0) out[(size_t)Bn * D + i] = red[0];
}

// ---------------- launch ----------------
extern "C" void kernel_launch(void* const* d_in, const int* in_sizes, int n_in,
                              void* d_out, int out_size) {
    const float* z    = (const float*)d_in[0];
    const float* W1   = (const float*)d_in[1];
    const float* b1   = (const float*)d_in[2];
    const float* W2   = (const float*)d_in[3];
    const float* b2   = (const float*)d_in[4];
    const int*   perm = (const int*)d_in[5];

    const int D  = in_sizes[5];      // 1024
    const int H  = in_sizes[2];      // 4096
    const int N2 = in_sizes[4];      // 2048
    const int B  = in_sizes[0] / D;  // 4096

    cudaFuncSetAttribute(gemm_mma<1>, cudaFuncAttributeMaxDynamicSharedMemorySize, SM_TOTAL);
    cudaFuncSetAttribute(gemm_mma<2>, cudaFuncAttributeMaxDynamicSharedMemorySize, SM_TOTAL);

    __nv_bfloat16 *zhi, *zlo, *w1hi, *w1lo, *hhi, *hlo, *w2hi, *w2lo;
    float* res;
    cudaGetSymbolAddress((void**)&zhi,  g_zhi);
    cudaGetSymbolAddress((void**)&zlo,  g_zlo);
    cudaGetSymbolAddress((void**)&w1hi, g_w1hi);
    cudaGetSymbolAddress((void**)&w1lo, g_w1lo);
    cudaGetSymbolAddress((void**)&hhi,  g_hhi);
    cudaGetSymbolAddress((void**)&hlo,  g_hlo);
    cudaGetSymbolAddress((void**)&w2hi, g_w2hi);
    cudaGetSymbolAddress((void**)&w2lo, g_w2lo);
    cudaGetSymbolAddress((void**)&res,  g_res);

    build_inv<<<(D + 255) / 256, 256>>>(perm, D);
    split_z_kernel<<<(long)B * D / 256, 256>>>(z, perm, D, (long)B * D);
    prep_w_kernel<<<dim3(H / 32, D / 32),  dim3(32, 8)>>>(W1, w1hi, w1lo, D, H, 1);
    prep_w_kernel<<<dim3(N2 / 32, H / 32), dim3(32, 8)>>>(W2, w2hi, w2lo, H, N2, 2);

    // GEMM1: [B,D] x [D,H]^T-packed -> h (bf16 split)
    gemm_mma<1><<<dim3(H / 128, B / 128), 256, SM_TOTAL>>>(
        zhi, zlo, w1hi, w1lo, b1, D, H, nullptr, hhi, hlo);
    // GEMM2: [B,H] x [H,2D]^T-packed -> res (fp32)
    gemm_mma<2><<<dim3(N2 / 128, B / 128), 256, SM_TOTAL>>>(
        hhi, hlo, w2hi, w2lo, b2, H, N2, res, nullptr, nullptr);

    finish_kernel<<<B, 256>>>(z, perm, (float*)d_out, B, D);
}

// round 7
// speedup vs baseline: 3.8485x; 1.0303x over previous
#include <cuda_runtime.h>
#include <cuda_bf16.h>
#include <cstdint>

// ============================================================
// MADE/IAF flow step on tensor cores via mma.sync (bf16, HMMA),
// fp32 accuracy via 3-term bf16 split: x*y ~= hi*hi + lo*hi + hi*lo
// + MADE-mask block sparsity (exact k-chunk skipping, ~44%).
// R7: 4-warp CTAs with 64x64 warp tiles, 2 CTAs/SM, vectorized prep.
// GEMM1: h = relu(zp @ (W1*M1) + b1)   [4096,1024]x[1024,4096]
// GEMM2: res = h @ (W2*M2) + b2        [4096,4096]x[4096,2048]
// finish: x = zp*exp(log_s)+mu (inv-permuted), log_det = row-sum
// ============================================================

// ---------------- device scratch (no allocs allowed) ----------------
__device__ float         g_res[4096ull * 2048ull];   // gemm2 out (fp32)
__device__ int           g_inv[4096];
__device__ __nv_bfloat16 g_zhi[4096ull * 1024ull], g_zlo[4096ull * 1024ull];   // [B,D]
__device__ __nv_bfloat16 g_w1hi[4096ull * 1024ull], g_w1lo[4096ull * 1024ull]; // [N=4096,K=1024]
__device__ __nv_bfloat16 g_hhi[4096ull * 4096ull], g_hlo[4096ull * 4096ull];   // [B,H]
__device__ __nv_bfloat16 g_w2hi[2048ull * 4096ull], g_w2lo[2048ull * 4096ull]; // [N=2048,K=4096]

// ---------------- PTX helpers (all baseline sm_80+ PTX) ----------------
__device__ __forceinline__ uint32_t smem_u32(const void* p) {
    uint32_t a;
    asm("{ .reg .u64 t; cvta.to.shared.u64 t, %1; cvt.u32.u64 %0, t; }" : "=r"(a) : "l"(p));
    return a;
}
__device__ __forceinline__ void cp16(uint32_t s, const void* g) {
    asm volatile("cp.async.cg.shared.global [%0], [%1], 16;" :: "r"(s), "l"(g));
}
__device__ __forceinline__ void cp_commit() {
    asm volatile("cp.async.commit_group;" ::: "memory");
}
__device__ __forceinline__ void cp_wait1() {
    asm volatile("cp.async.wait_group 1;" ::: "memory");
}
__device__ __forceinline__ void ldm_x4(uint32_t addr, uint32_t* r) {
    asm volatile("ldmatrix.sync.aligned.m8n8.x4.shared.b16 {%0,%1,%2,%3}, [%4];"
                 : "=r"(r[0]), "=r"(r[1]), "=r"(r[2]), "=r"(r[3]) : "r"(addr));
}
__device__ __forceinline__ void mma16816(float* c, const uint32_t* a, const uint32_t* b) {
    asm volatile(
        "mma.sync.aligned.m16n8k16.row.col.f32.bf16.bf16.f32 "
        "{%0,%1,%2,%3}, {%4,%5,%6,%7}, {%8,%9}, {%0,%1,%2,%3};"
        : "+f"(c[0]), "+f"(c[1]), "+f"(c[2]), "+f"(c[3])
        : "r"(a[0]), "r"(a[1]), "r"(a[2]), "r"(a[3]), "r"(b[0]), "r"(b[1]));
}

// ---------------- prep kernels ----------------
__global__ void build_inv(const int* __restrict__ perm, int D) {
    int d = blockIdx.x * blockDim.x + threadIdx.x;
    if (d < D) g_inv[perm[d]] = d;
}

__global__ void split_z_kernel(const float* __restrict__ z, const int* __restrict__ perm,
                               int D, long total) {
    long idx = (long)blockIdx.x * blockDim.x + threadIdx.x;
    if (idx >= total) return;
    int i = (int)(idx >> 10);      // D = 1024
    int k = (int)(idx & 1023);
    float v = z[(size_t)i * D + perm[k]];
    __nv_bfloat16 hi = __float2bfloat16(v);
    __nv_bfloat16 lo = __float2bfloat16(v - __bfloat162float(hi));
    g_zhi[idx] = hi;
    g_zlo[idx] = lo;
}

// mask+transpose+split, vectorized: W [K,N] fp32 -> out [N,K] bf16 hi/lo.
// 64x64 tiles; float4 global reads; 32B (8x bf16x2) global writes.
// mode 1: mask = (n % 1023) >= k          (W1/M1)
// mode 2: mask = (n % 1024) > (k % 1023)  (W2/M2)
__global__ __launch_bounds__(256) void prep_w_kernel(
    const float* __restrict__ W,
    __nv_bfloat16* __restrict__ oHi, __nv_bfloat16* __restrict__ oLo,
    int K, int N, int mode) {
    __shared__ float tile[64][65];
    const int n0 = blockIdx.x * 64;
    const int k0 = blockIdx.y * 64;
    const int tid = threadIdx.x;
#pragma unroll
    for (int it = 0; it < 4; it++) {
        int lin = tid + it * 256;          // 1024 float4 loads
        int k = lin >> 4;
        int n4 = (lin & 15) << 2;
        float4 v = *reinterpret_cast<const float4*>(&W[(size_t)(k0 + k) * N + n0 + n4]);
        tile[k][n4 + 0] = v.x;
        tile[k][n4 + 1] = v.y;
        tile[k][n4 + 2] = v.z;
        tile[k][n4 + 3] = v.w;
    }
    __syncthreads();
    const int tn = tid & 63;
    const int kg = tid >> 6;               // 0..3, 16 k each
    const int n  = n0 + tn;
    const int jm = (mode == 1) ? (n % 1023) : (n & 1023);
    uint32_t hibuf[8], lobuf[8];
#pragma unroll
    for (int e = 0; e < 8; e++) {
        float v0, v1;
        {
            int k = k0 + kg * 16 + 2 * e;
            float v = tile[kg * 16 + 2 * e][tn];
            bool m = (mode == 1) ? (jm >= k) : (jm > (k % 1023));
            v0 = m ? v : 0.f;
        }
        {
            int k = k0 + kg * 16 + 2 * e + 1;
            float v = tile[kg * 16 + 2 * e + 1][tn];
            bool m = (mode == 1) ? (jm >= k) : (jm > (k % 1023));
            v1 = m ? v : 0.f;
        }
        __nv_bfloat16 h0 = __float2bfloat16(v0);
        __nv_bfloat16 h1 = __float2bfloat16(v1);
        __nv_bfloat16 l0 = __float2bfloat16(v0 - __bfloat162float(h0));
        __nv_bfloat16 l1 = __float2bfloat16(v1 - __bfloat162float(h1));
        __nv_bfloat162 ph; ph.x = h0; ph.y = h1;
        __nv_bfloat162 pl; pl.x = l0; pl.y = l1;
        hibuf[e] = *reinterpret_cast<uint32_t*>(&ph);
        lobuf[e] = *reinterpret_cast<uint32_t*>(&pl);
    }
    const size_t ob = (size_t)n * K + k0 + kg * 16;
    *reinterpret_cast<uint4*>(oHi + ob)     = *reinterpret_cast<uint4*>(hibuf);
    *reinterpret_cast<uint4*>(oHi + ob + 8) = *reinterpret_cast<uint4*>(hibuf + 4);
    *reinterpret_cast<uint4*>(oLo + ob)     = *reinterpret_cast<uint4*>(lobuf);
    *reinterpret_cast<uint4*>(oLo + ob + 8) = *reinterpret_cast<uint4*>(lobuf + 4);
}

// ---------------- mma.sync GEMM (3-term bf16 split, chunk skipping) ----------------
// C[m,n] = sum_k A[m,k]*B[n,k]; A [M,K] row-major hi/lo, B [N,K] row-major hi/lo.
// CTA tile 128x128, K-chunk 32, 4 warps (2x2), warp tile 64x64, 3-stage cp.async,
// 2 CTAs/SM. Smem row: 128B = [0,64) hi k0..31, [64,128) lo, XOR-swizzled:
// byte = row*128 + (inner ^ ((row&7)<<4)).
#define SA_BYTES   16384
#define STG_BYTES  32768
#define SM_TOTAL   (3 * STG_BYTES + 1024)
#define NTHR       128

template <int MODE>
__global__ __launch_bounds__(NTHR) void gemm_mma(
    const __nv_bfloat16* __restrict__ Ahi, const __nv_bfloat16* __restrict__ Alo,
    const __nv_bfloat16* __restrict__ Bhi, const __nv_bfloat16* __restrict__ Blo,
    const float* __restrict__ bias, int K, int Nout,
    float* __restrict__ outF,
    __nv_bfloat16* __restrict__ outHi, __nv_bfloat16* __restrict__ outLo)
{
    extern __shared__ char smem[];
    const uint32_t sb = smem_u32(smem);
    int* kt = (int*)(smem + 3 * STG_BYTES);
    const int tid  = threadIdx.x;
    const int lane = tid & 31;
    const int w    = tid >> 5;
    const int wm   = w & 1;        // 2 warps in M
    const int wn   = w >> 1;       // 2 warps in N
    const int row0 = blockIdx.y * 128;
    const int col0 = blockIdx.x * 128;
    const int nk   = K >> 5;

    // ---- build kept-chunk list (mask-induced block sparsity) ----
    if (tid == 0) {
        int c = 0;
        for (int t = 0; t < nk; t++) {
            const int k0 = t << 5;
            bool keep;
            if (MODE == 1) {
                int c0 = col0 % 1023;
                int jmmax = (c0 + 127 > 1022) ? 1022 : (c0 + 127);
                keep = (k0 <= jmmax);
            } else {
                int km0 = k0 % 1023;
                int jdmax = (col0 & 1023) + 127;
                keep = (km0 < jdmax) || (km0 > 991);
            }
            if (keep) kt[c++] = t;
        }
        kt[255] = c;
    }
    __syncthreads();
    const int cnt = kt[255];

    float acc[4][8][4];
#pragma unroll
    for (int mt = 0; mt < 4; mt++)
#pragma unroll
        for (int nt = 0; nt < 8; nt++)
#pragma unroll
            for (int e = 0; e < 4; e++) acc[mt][nt][e] = 0.f;

    auto load_stage = [&](int chunk, int slot) {
        const int k0 = chunk << 5;
        const uint32_t s0 = sb + slot * STG_BYTES;
#pragma unroll
        for (int i = 0; i < 8; i++) {
            int idx = tid + i * NTHR;
            int row = idx >> 3, cc = idx & 7;
            const __nv_bfloat16* src =
                ((cc < 4) ? Ahi : Alo) + (size_t)(row0 + row) * K + k0 + (cc & 3) * 8;
            cp16(s0 + row * 128 + ((cc * 16) ^ ((row & 7) << 4)), src);
        }
#pragma unroll
        for (int i = 0; i < 8; i++) {
            int idx = tid + i * NTHR;
            int row = idx >> 3, cc = idx & 7;
            const __nv_bfloat16* src =
                ((cc < 4) ? Bhi : Blo) + (size_t)(col0 + row) * K + k0 + (cc & 3) * 8;
            cp16(s0 + SA_BYTES + row * 128 + ((cc * 16) ^ ((row & 7) << 4)), src);
        }
    };

    load_stage(kt[0], 0);
    cp_commit();
    if (cnt > 1) load_stage(kt[1], 1);
    cp_commit();

    // fragment address components (per-thread constants)
    int rA[4], xA[4];
#pragma unroll
    for (int mt = 0; mt < 4; mt++) {
        int r = wm * 64 + mt * 16 + (lane & 15);
        rA[mt] = r * 128;
        xA[mt] = (r & 7) << 4;
    }
    const int kA2 = (lane >> 4) << 4;          // A k-byte offset part (0 or 16)
    int rB[4], xB[4];
#pragma unroll
    for (int p = 0; p < 4; p++) {
        int r = wn * 64 + p * 16 + (lane & 7) + ((lane & 16) >> 1);
        rB[p] = r * 128;
        xB[p] = (r & 7) << 4;
    }
    const int kB2 = (lane & 8) << 1;           // B k-byte offset part (0 or 16)

    for (int i = 0; i < cnt; i++) {
        cp_wait1();
        __syncthreads();
        if (i + 2 < cnt) load_stage(kt[i + 2], (i + 2) % 3);
        cp_commit();

        const uint32_t sA = sb + (i % 3) * STG_BYTES;
        const uint32_t sB = sA + SA_BYTES;
#pragma unroll
        for (int ks = 0; ks < 2; ks++) {
            const int kbA = ks * 32 + kA2;
            const int kbB = ks * 32 + kB2;
            uint32_t Ah[4][4], Al[4][4];
#pragma unroll
            for (int mt = 0; mt < 4; mt++)
                ldm_x4(sA + rA[mt] + (kbA ^ xA[mt]), Ah[mt]);
#pragma unroll
            for (int mt = 0; mt < 4; mt++)
                ldm_x4(sA + rA[mt] + ((64 + kbA) ^ xA[mt]), Al[mt]);
            // B processed pair-of-nt at a time to bound live registers
#pragma unroll
            for (int p = 0; p < 4; p++) {
                uint32_t bh[4], bl[4];
                ldm_x4(sB + rB[p] + (kbB ^ xB[p]), bh);
                ldm_x4(sB + rB[p] + ((64 + kbB) ^ xB[p]), bl);
#pragma unroll
                for (int half = 0; half < 2; half++) {
                    const int nt = 2 * p + half;
                    const uint32_t* Bh2 = bh + 2 * half;
                    const uint32_t* Bl2 = bl + 2 * half;
#pragma unroll
                    for (int mt = 0; mt < 4; mt++) {
                        mma16816(acc[mt][nt], Ah[mt], Bh2);   // hi*hi
                        mma16816(acc[mt][nt], Al[mt], Bh2);   // lo*hi
                        mma16816(acc[mt][nt], Ah[mt], Bl2);   // hi*lo
                    }
                }
            }
        }
    }

    // epilogue
    const int mrow = lane >> 2;
    const int mcol = (lane & 3) * 2;
#pragma unroll
    for (int mt = 0; mt < 4; mt++) {
        const int rbase = row0 + wm * 64 + mt * 16 + mrow;
#pragma unroll
        for (int nt = 0; nt < 8; nt++) {
            const int c = col0 + wn * 64 + nt * 8 + mcol;
            const float b0 = bias[c], b1 = bias[c + 1];
#pragma unroll
            for (int h = 0; h < 2; h++) {
                const int r = rbase + h * 8;
                float v0 = acc[mt][nt][2 * h + 0] + b0;
                float v1 = acc[mt][nt][2 * h + 1] + b1;
                const size_t o = (size_t)r * Nout + c;
                if (MODE == 1) {
                    v0 = fmaxf(v0, 0.f);
                    v1 = fmaxf(v1, 0.f);
                    __nv_bfloat16 h0 = __float2bfloat16(v0);
                    __nv_bfloat16 h1 = __float2bfloat16(v1);
                    __nv_bfloat16 l0 = __float2bfloat16(v0 - __bfloat162float(h0));
                    __nv_bfloat16 l1 = __float2bfloat16(v1 - __bfloat162float(h1));
                    __nv_bfloat162 ph; ph.x = h0; ph.y = h1;
                    __nv_bfloat162 pl; pl.x = l0; pl.y = l1;
                    *(__nv_bfloat162*)(outHi + o) = ph;
                    *(__nv_bfloat162*)(outLo + o) = pl;
                } else {
                    *(float2*)(outF + o) = make_float2(v0, v1);
                }
            }
        }
    }
}

// ---------------- finish ----------------
__global__ void finish_kernel(const float* __restrict__ z,
                              const int* __restrict__ perm,
                              float* __restrict__ out,
                              int Bn, int D)
{
    const int i = blockIdx.x;
    const int t = threadIdx.x;
    __shared__ float red[256];

    const float* resrow = &g_res[(size_t)i * 2 * D];
    const float* zrow   = &z[(size_t)i * D];

    float s = 0.f;
    for (int d = t; d < D; d += blockDim.x) s += resrow[D + d];

    for (int j = t; j < D; j += blockDim.x) {
        int dj   = g_inv[j];
        float ls = resrow[D + dj];
        float mu = resrow[dj];
        float zp = zrow[perm[dj]];
        out[(size_t)i * D + j] = fmaf(zp, expf(ls), mu);
    }

    red[t] = s;
    __syncthreads();
    for (int off = 128; off > 0; off >>= 1) {
        if (t < off) red[t] += red[t + off];
        __syncthreads();
    }
    if (t == 0) out[(size_t)Bn * D + i] = red[0];
}

// ---------------- launch ----------------
extern "C" void kernel_launch(void* const* d_in, const int* in_sizes, int n_in,
                              void* d_out, int out_size) {
    const float* z    = (const float*)d_in[0];
    const float* W1   = (const float*)d_in[1];
    const float* b1   = (const float*)d_in[2];
    const float* W2   = (const float*)d_in[3];
    const float* b2   = (const float*)d_in[4];
    const int*   perm = (const int*)d_in[5];

    const int D  = in_sizes[5];      // 1024
    const int H  = in_sizes[2];      // 4096
    const int N2 = in_sizes[4];      // 2048
    const int B  = in_sizes[0] / D;  // 4096

    cudaFuncSetAttribute(gemm_mma<1>, cudaFuncAttributeMaxDynamicSharedMemorySize, SM_TOTAL);
    cudaFuncSetAttribute(gemm_mma<2>, cudaFuncAttributeMaxDynamicSharedMemorySize, SM_TOTAL);

    __nv_bfloat16 *zhi, *zlo, *w1hi, *w1lo, *hhi, *hlo, *w2hi, *w2lo;
    float* res;
    cudaGetSymbolAddress((void**)&zhi,  g_zhi);
    cudaGetSymbolAddress((void**)&zlo,  g_zlo);
    cudaGetSymbolAddress((void**)&w1hi, g_w1hi);
    cudaGetSymbolAddress((void**)&w1lo, g_w1lo);
    cudaGetSymbolAddress((void**)&hhi,  g_hhi);
    cudaGetSymbolAddress((void**)&hlo,  g_hlo);
    cudaGetSymbolAddress((void**)&w2hi, g_w2hi);
    cudaGetSymbolAddress((void**)&w2lo, g_w2lo);
    cudaGetSymbolAddress((void**)&res,  g_res);

    build_inv<<<(D + 255) / 256, 256>>>(perm, D);
    split_z_kernel<<<(long)B * D / 256, 256>>>(z, perm, D, (long)B * D);
    prep_w_kernel<<<dim3(H / 64, D / 64),  256>>>(W1, w1hi, w1lo, D, H, 1);
    prep_w_kernel<<<dim3(N2 / 64, H / 64), 256>>>(W2, w2hi, w2lo, H, N2, 2);

    // GEMM1: [B,D] x [D,H]^T-packed -> h (bf16 split)
    gemm_mma<1><<<dim3(H / 128, B / 128), NTHR, SM_TOTAL>>>(
        zhi, zlo, w1hi, w1lo, b1, D, H, nullptr, hhi, hlo);
    // GEMM2: [B,H] x [H,2D]^T-packed -> res (fp32)
    gemm_mma<2><<<dim3(N2 / 128, B / 128), NTHR, SM_TOTAL>>>(
        hhi, hlo, w2hi, w2lo, b2, H, N2, res, nullptr, nullptr);

    finish_kernel<<<B, 256>>>(z, perm, (float*)d_out, B, D);
}

// round 8
// speedup vs baseline: 5.4424x; 1.4142x over previous
#include <cuda_runtime.h>
#include <cuda_fp16.h>
#include <cstdint>

// ============================================================
// MADE/IAF flow step on tensor cores via mma.sync (fp16 HMMA).
// Accuracy: 2-term fp16 split of the ACTIVATION operand only:
//   A ~= Ahi + Alo (fp16 pair, exact to 2^-22), B = W in fp16.
//   A*B ~= Ahi*Bhi + Alo*Bhi   (dropped Ahi*Berr ~ 2^-11/sqrt3)
// + MADE-mask block sparsity (exact k-chunk skipping, ~44%).
// GEMM1: h = relu(zp @ (W1*M1) + b1)   [4096,1024]x[1024,4096]
// GEMM2: res = h @ (W2*M2) + b2        [4096,4096]x[4096,2048]
// finish: x = zp*exp(log_s)+mu (inv-permuted), log_det = row-sum
// ============================================================

// ---------------- device scratch (no allocs allowed) ----------------
__device__ float  g_res[4096ull * 2048ull];   // gemm2 out (fp32)
__device__ int    g_inv[4096];
__device__ __half g_zhi[4096ull * 1024ull], g_zlo[4096ull * 1024ull];  // [B,D]
__device__ __half g_w1hi[4096ull * 1024ull];                           // [N=4096,K=1024]
__device__ __half g_hhi[4096ull * 4096ull], g_hlo[4096ull * 4096ull];  // [B,H]
__device__ __half g_w2hi[2048ull * 4096ull];                           // [N=2048,K=4096]

// ---------------- PTX helpers (all baseline sm_80+ PTX) ----------------
__device__ __forceinline__ uint32_t smem_u32(const void* p) {
    uint32_t a;
    asm("{ .reg .u64 t; cvta.to.shared.u64 t, %1; cvt.u32.u64 %0, t; }" : "=r"(a) : "l"(p));
    return a;
}
__device__ __forceinline__ void cp16(uint32_t s, const void* g) {
    asm volatile("cp.async.cg.shared.global [%0], [%1], 16;" :: "r"(s), "l"(g));
}
__device__ __forceinline__ void cp_commit() {
    asm volatile("cp.async.commit_group;" ::: "memory");
}
__device__ __forceinline__ void cp_wait1() {
    asm volatile("cp.async.wait_group 1;" ::: "memory");
}
__device__ __forceinline__ void ldm_x4(uint32_t addr, uint32_t* r) {
    asm volatile("ldmatrix.sync.aligned.m8n8.x4.shared.b16 {%0,%1,%2,%3}, [%4];"
                 : "=r"(r[0]), "=r"(r[1]), "=r"(r[2]), "=r"(r[3]) : "r"(addr));
}
__device__ __forceinline__ void mma16816(float* c, const uint32_t* a, const uint32_t* b) {
    asm volatile(
        "mma.sync.aligned.m16n8k16.row.col.f32.f16.f16.f32 "
        "{%0,%1,%2,%3}, {%4,%5,%6,%7}, {%8,%9}, {%0,%1,%2,%3};"
        : "+f"(c[0]), "+f"(c[1]), "+f"(c[2]), "+f"(c[3])
        : "r"(a[0]), "r"(a[1]), "r"(a[2]), "r"(a[3]), "r"(b[0]), "r"(b[1]));
}

// ---------------- prep kernels ----------------
__global__ void build_inv(const int* __restrict__ perm, int D) {
    int d = blockIdx.x * blockDim.x + threadIdx.x;
    if (d < D) g_inv[perm[d]] = d;
}

__global__ void split_z_kernel(const float* __restrict__ z, const int* __restrict__ perm,
                               int D, long total) {
    long idx = (long)blockIdx.x * blockDim.x + threadIdx.x;
    if (idx >= total) return;
    int i = (int)(idx >> 10);      // D = 1024
    int k = (int)(idx & 1023);
    float v = z[(size_t)i * D + perm[k]];
    __half hi = __float2half(v);
    __half lo = __float2half(v - __half2float(hi));
    g_zhi[idx] = hi;
    g_zlo[idx] = lo;
}

// mask+transpose to fp16: W [K,N] fp32 -> out [N,K] fp16 (hi only).
// 64x64 tiles; float4 global reads; 32B global writes.
// mode 1: mask = (n % 1023) >= k          (W1/M1)
// mode 2: mask = (n % 1024) > (k % 1023)  (W2/M2)
__global__ __launch_bounds__(256) void prep_w_kernel(
    const float* __restrict__ W, __half* __restrict__ oHi,
    int K, int N, int mode) {
    __shared__ float tile[64][65];
    const int n0 = blockIdx.x * 64;
    const int k0 = blockIdx.y * 64;
    const int tid = threadIdx.x;
#pragma unroll
    for (int it = 0; it < 4; it++) {
        int lin = tid + it * 256;          // 1024 float4 loads
        int k = lin >> 4;
        int n4 = (lin & 15) << 2;
        float4 v = *reinterpret_cast<const float4*>(&W[(size_t)(k0 + k) * N + n0 + n4]);
        tile[k][n4 + 0] = v.x;
        tile[k][n4 + 1] = v.y;
        tile[k][n4 + 2] = v.z;
        tile[k][n4 + 3] = v.w;
    }
    __syncthreads();
    const int tn = tid & 63;
    const int kg = tid >> 6;               // 0..3, 16 k each
    const int n  = n0 + tn;
    const int jm = (mode == 1) ? (n % 1023) : (n & 1023);
    uint32_t hibuf[8];
#pragma unroll
    for (int e = 0; e < 8; e++) {
        float v0, v1;
        {
            int k = k0 + kg * 16 + 2 * e;
            float v = tile[kg * 16 + 2 * e][tn];
            bool m = (mode == 1) ? (jm >= k) : (jm > (k % 1023));
            v0 = m ? v : 0.f;
        }
        {
            int k = k0 + kg * 16 + 2 * e + 1;
            float v = tile[kg * 16 + 2 * e + 1][tn];
            bool m = (mode == 1) ? (jm >= k) : (jm > (k % 1023));
            v1 = m ? v : 0.f;
        }
        __half2 ph; ph.x = __float2half(v0); ph.y = __float2half(v1);
        hibuf[e] = *reinterpret_cast<uint32_t*>(&ph);
    }
    const size_t ob = (size_t)n * K + k0 + kg * 16;
    *reinterpret_cast<uint4*>(oHi + ob)     = *reinterpret_cast<uint4*>(hibuf);
    *reinterpret_cast<uint4*>(oHi + ob + 8) = *reinterpret_cast<uint4*>(hibuf + 4);
}

// ---------------- mma.sync GEMM (2-term fp16 split, chunk skipping) ----------------
// C[m,n] = sum_k A[m,k]*B[n,k]; A [M,K] row-major hi/lo fp16, B [N,K] fp16.
// CTA tile 128x128, K-chunk 32, 4 warps (2x2), warp tile 64x64, 3-stage cp.async,
// 2 CTAs/SM. Smem rows 128B, XOR-swizzled: byte = row*128 + (inner ^ ((row&7)<<4)).
// A rows: [0,64) hi, [64,128) lo. B rows: only the kb<64 swizzle-image slots hold hi.
#define SA_BYTES   16384
#define STG_BYTES  32768
#define SM_TOTAL   (3 * STG_BYTES + 1024)
#define NTHR       128

template <int MODE>
__global__ __launch_bounds__(NTHR) void gemm_mma(
    const __half* __restrict__ Ahi, const __half* __restrict__ Alo,
    const __half* __restrict__ Bhi,
    const float* __restrict__ bias, int K, int Nout,
    float* __restrict__ outF,
    __half* __restrict__ outHi, __half* __restrict__ outLo)
{
    extern __shared__ char smem[];
    const uint32_t sb = smem_u32(smem);
    int* kt = (int*)(smem + 3 * STG_BYTES);
    const int tid  = threadIdx.x;
    const int lane = tid & 31;
    const int w    = tid >> 5;
    const int wm   = w & 1;        // 2 warps in M
    const int wn   = w >> 1;       // 2 warps in N
    const int row0 = blockIdx.y * 128;
    const int col0 = blockIdx.x * 128;
    const int nk   = K >> 5;

    // ---- build kept-chunk list (mask-induced block sparsity) ----
    if (tid == 0) {
        int c = 0;
        for (int t = 0; t < nk; t++) {
            const int k0 = t << 5;
            bool keep;
            if (MODE == 1) {
                int c0 = col0 % 1023;
                int jmmax = (c0 + 127 > 1022) ? 1022 : (c0 + 127);
                keep = (k0 <= jmmax);
            } else {
                int km0 = k0 % 1023;
                int jdmax = (col0 & 1023) + 127;
                keep = (km0 < jdmax) || (km0 > 991);
            }
            if (keep) kt[c++] = t;
        }
        kt[255] = c;
    }
    __syncthreads();
    const int cnt = kt[255];

    float acc[4][8][4];
#pragma unroll
    for (int mt = 0; mt < 4; mt++)
#pragma unroll
        for (int nt = 0; nt < 8; nt++)
#pragma unroll
            for (int e = 0; e < 4; e++) acc[mt][nt][e] = 0.f;

    auto load_stage = [&](int chunk, int slot) {
        const int k0 = chunk << 5;
        const uint32_t s0 = sb + slot * STG_BYTES;
        // A: 128 rows x (hi 64B + lo 64B) = 1024 cp16
#pragma unroll
        for (int i = 0; i < 8; i++) {
            int idx = tid + i * NTHR;
            int row = idx >> 3, cc = idx & 7;
            const __half* src =
                ((cc < 4) ? Ahi : Alo) + (size_t)(row0 + row) * K + k0 + (cc & 3) * 8;
            cp16(s0 + row * 128 + ((cc * 16) ^ ((row & 7) << 4)), src);
        }
        // B: 128 rows x hi 64B = 512 cp16 (lo slots never written or read)
#pragma unroll
        for (int i = 0; i < 4; i++) {
            int idx = tid + i * NTHR;
            int row = idx >> 2, cc = idx & 3;
            const __half* src = Bhi + (size_t)(col0 + row) * K + k0 + cc * 8;
            cp16(s0 + SA_BYTES + row * 128 + ((cc * 16) ^ ((row & 7) << 4)), src);
        }
    };

    load_stage(kt[0], 0);
    cp_commit();
    if (cnt > 1) load_stage(kt[1], 1);
    cp_commit();

    // fragment address components (per-thread constants)
    int rA[4], xA[4];
#pragma unroll
    for (int mt = 0; mt < 4; mt++) {
        int r = wm * 64 + mt * 16 + (lane & 15);
        rA[mt] = r * 128;
        xA[mt] = (r & 7) << 4;
    }
    const int kA2 = (lane >> 4) << 4;          // A k-byte offset part (0 or 16)
    int rB[4], xB[4];
#pragma unroll
    for (int p = 0; p < 4; p++) {
        int r = wn * 64 + p * 16 + (lane & 7) + ((lane & 16) >> 1);
        rB[p] = r * 128;
        xB[p] = (r & 7) << 4;
    }
    const int kB2 = (lane & 8) << 1;           // B k-byte offset part (0 or 16)

    for (int i = 0; i < cnt; i++) {
        cp_wait1();
        __syncthreads();
        if (i + 2 < cnt) load_stage(kt[i + 2], (i + 2) % 3);
        cp_commit();

        const uint32_t sA = sb + (i % 3) * STG_BYTES;
        const uint32_t sB = sA + SA_BYTES;
#pragma unroll
        for (int ks = 0; ks < 2; ks++) {
            const int kbA = ks * 32 + kA2;
            const int kbB = ks * 32 + kB2;
            uint32_t Ah[4][4], Al[4][4];
#pragma unroll
            for (int mt = 0; mt < 4; mt++)
                ldm_x4(sA + rA[mt] + (kbA ^ xA[mt]), Ah[mt]);
#pragma unroll
            for (int mt = 0; mt < 4; mt++)
                ldm_x4(sA + rA[mt] + ((64 + kbA) ^ xA[mt]), Al[mt]);
#pragma unroll
            for (int p = 0; p < 4; p++) {
                uint32_t bh[4];
                ldm_x4(sB + rB[p] + (kbB ^ xB[p]), bh);
#pragma unroll
                for (int half = 0; half < 2; half++) {
                    const int nt = 2 * p + half;
                    const uint32_t* Bh2 = bh + 2 * half;
#pragma unroll
                    for (int mt = 0; mt < 4; mt++) {
                        mma16816(acc[mt][nt], Ah[mt], Bh2);   // hi*hi
                        mma16816(acc[mt][nt], Al[mt], Bh2);   // lo*hi
                    }
                }
            }
        }
    }

    // epilogue
    const int mrow = lane >> 2;
    const int mcol = (lane & 3) * 2;
#pragma unroll
    for (int mt = 0; mt < 4; mt++) {
        const int rbase = row0 + wm * 64 + mt * 16 + mrow;
#pragma unroll
        for (int nt = 0; nt < 8; nt++) {
            const int c = col0 + wn * 64 + nt * 8 + mcol;
            const float b0 = bias[c], b1 = bias[c + 1];
#pragma unroll
            for (int h = 0; h < 2; h++) {
                const int r = rbase + h * 8;
                float v0 = acc[mt][nt][2 * h + 0] + b0;
                float v1 = acc[mt][nt][2 * h + 1] + b1;
                const size_t o = (size_t)r * Nout + c;
                if (MODE == 1) {
                    v0 = fmaxf(v0, 0.f);
                    v1 = fmaxf(v1, 0.f);
                    __half h0 = __float2half(v0);
                    __half h1 = __float2half(v1);
                    __half l0 = __float2half(v0 - __half2float(h0));
                    __half l1 = __float2half(v1 - __half2float(h1));
                    __half2 ph; ph.x = h0; ph.y = h1;
                    __half2 pl; pl.x = l0; pl.y = l1;
                    *(__half2*)(outHi + o) = ph;
                    *(__half2*)(outLo + o) = pl;
                } else {
                    *(float2*)(outF + o) = make_float2(v0, v1);
                }
            }
        }
    }
}

// ---------------- finish ----------------
__global__ void finish_kernel(const float* __restrict__ z,
                              const int* __restrict__ perm,
                              float* __restrict__ out,
                              int Bn, int D)
{
    const int i = blockIdx.x;
    const int t = threadIdx.x;
    __shared__ float red[256];

    const float* resrow = &g_res[(size_t)i * 2 * D];
    const float* zrow   = &z[(size_t)i * D];

    float s = 0.f;
    for (int d = t; d < D; d += blockDim.x) s += resrow[D + d];

    for (int j = t; j < D; j += blockDim.x) {
        int dj   = g_inv[j];
        float ls = resrow[D + dj];
        float mu = resrow[dj];
        float zp = zrow[perm[dj]];
        out[(size_t)i * D + j] = fmaf(zp, expf(ls), mu);
    }

    red[t] = s;
    __syncthreads();
    for (int off = 128; off > 0; off >>= 1) {
        if (t < off) red[t] += red[t + off];
        __syncthreads();
    }
    if (t == 0) out[(size_t)Bn * D + i] = red[0];
}

// ---------------- launch ----------------
extern "C" void kernel_launch(void* const* d_in, const int* in_sizes, int n_in,
                              void* d_out, int out_size) {
    const float* z    = (const float*)d_in[0];
    const float* W1   = (const float*)d_in[1];
    const float* b1   = (const float*)d_in[2];
    const float* W2   = (const float*)d_in[3];
    const float* b2   = (const float*)d_in[4];
    const int*   perm = (const int*)d_in[5];

    const int D  = in_sizes[5];      // 1024
    const int H  = in_sizes[2];      // 4096
    const int N2 = in_sizes[4];      // 2048
    const int B  = in_sizes[0] / D;  // 4096

    cudaFuncSetAttribute(gemm_mma<1>, cudaFuncAttributeMaxDynamicSharedMemorySize, SM_TOTAL);
    cudaFuncSetAttribute(gemm_mma<2>, cudaFuncAttributeMaxDynamicSharedMemorySize, SM_TOTAL);

    __half *zhi, *zlo, *w1hi, *hhi, *hlo, *w2hi;
    float* res;
    cudaGetSymbolAddress((void**)&zhi,  g_zhi);
    cudaGetSymbolAddress((void**)&zlo,  g_zlo);
    cudaGetSymbolAddress((void**)&w1hi, g_w1hi);
    cudaGetSymbolAddress((void**)&hhi,  g_hhi);
    cudaGetSymbolAddress((void**)&hlo,  g_hlo);
    cudaGetSymbolAddress((void**)&w2hi, g_w2hi);
    cudaGetSymbolAddress((void**)&res,  g_res);

    build_inv<<<(D + 255) / 256, 256>>>(perm, D);
    split_z_kernel<<<(long)B * D / 256, 256>>>(z, perm, D, (long)B * D);
    prep_w_kernel<<<dim3(H / 64, D / 64),  256>>>(W1, w1hi, D, H, 1);
    prep_w_kernel<<<dim3(N2 / 64, H / 64), 256>>>(W2, w2hi, H, N2, 2);

    // GEMM1: [B,D] x [D,H]^T-packed -> h (fp16 split)
    gemm_mma<1><<<dim3(H / 128, B / 128), NTHR, SM_TOTAL>>>(
        zhi, zlo, w1hi, b1, D, H, nullptr, hhi, hlo);
    // GEMM2: [B,H] x [H,2D]^T-packed -> res (fp32)
    gemm_mma<2><<<dim3(N2 / 128, B / 128), NTHR, SM_TOTAL>>>(
        hhi, hlo, w2hi, b2, H, N2, res, nullptr, nullptr);

    finish_kernel<<<B, 256>>>(z, perm, (float*)d_out, B, D);
}